// round 1
// baseline (speedup 1.0000x reference)
#include <cuda_runtime.h>
#include <cuda_bf16.h>
#include <math_constants.h>

#define NPTS 262144
#define KNN  16

// ---------------- scratch (device globals; no allocation allowed) ----------
__device__ float d_h [ (size_t)NPTS * 64  ];   // mlp2 output  (67 MB)
__device__ float d_hc[ (size_t)NPTS * 192 ];   // [x_gm | h4]  (201 MB)
__device__ float d_g [1024];
__device__ float d_f1[512];
__device__ float d_f2[256];

// ---------------- init ------------------------------------------------------
__global__ void k_zero_g() {
    int t = blockIdx.x * blockDim.x + threadIdx.x;
    if (t < 1024) d_g[t] = 0.0f;
}

// ---------------- mlp1 + mlp2 : x[N,3] -> h[N,64] --------------------------
__global__ __launch_bounds__(256) void k_mlp12(const float* __restrict__ x,
                                               const float* __restrict__ w1,
                                               const float* __restrict__ w2) {
    __shared__ float w1s[64 * 3];
    __shared__ float w2s[64 * 64];
    for (int i = threadIdx.x; i < 192;  i += 256) w1s[i] = w1[i];
    for (int i = threadIdx.x; i < 4096; i += 256) w2s[i] = w2[i];
    __syncthreads();

    int p = blockIdx.x * 256 + threadIdx.x;
    float x0 = x[p * 3 + 0], x1 = x[p * 3 + 1], x2 = x[p * 3 + 2];

    float h1[64];
#pragma unroll
    for (int j = 0; j < 64; j++) {
        float a = x0 * w1s[j * 3] + x1 * w1s[j * 3 + 1] + x2 * w1s[j * 3 + 2];
        h1[j] = fmaxf(a, 0.0f);
    }

    float* out = d_h + (size_t)p * 64;
#pragma unroll
    for (int j = 0; j < 64; j += 4) {
        float a0 = 0.f, a1 = 0.f, a2 = 0.f, a3 = 0.f;
#pragma unroll
        for (int k = 0; k < 64; k += 4) {
            float4 b0 = *(const float4*)&w2s[(j + 0) * 64 + k];
            float4 b1 = *(const float4*)&w2s[(j + 1) * 64 + k];
            float4 b2 = *(const float4*)&w2s[(j + 2) * 64 + k];
            float4 b3 = *(const float4*)&w2s[(j + 3) * 64 + k];
            a0 += b0.x*h1[k] + b0.y*h1[k+1] + b0.z*h1[k+2] + b0.w*h1[k+3];
            a1 += b1.x*h1[k] + b1.y*h1[k+1] + b1.z*h1[k+2] + b1.w*h1[k+3];
            a2 += b2.x*h1[k] + b2.y*h1[k+1] + b2.z*h1[k+2] + b2.w*h1[k+3];
            a3 += b3.x*h1[k] + b3.y*h1[k+1] + b3.z*h1[k+2] + b3.w*h1[k+3];
        }
        float4 r = make_float4(fmaxf(a0,0.f), fmaxf(a1,0.f), fmaxf(a2,0.f), fmaxf(a3,0.f));
        *(float4*)&out[j] = r;
    }
}

// ---------------- graph max-pool: hc[:,0:64] = segmax_K h[indices] ---------
__global__ __launch_bounds__(256) void k_pool(const int* __restrict__ indices) {
    int warp = (blockIdx.x * blockDim.x + threadIdx.x) >> 5;
    int lane = threadIdx.x & 31;
    if (warp >= NPTS) return;
    int idx = indices[(size_t)warp * KNN + (lane & 15)];   // lanes 0-15 valid
    float2 m = make_float2(-CUDART_INF_F, -CUDART_INF_F);
#pragma unroll
    for (int k = 0; k < KNN; k++) {
        int nb = __shfl_sync(0xffffffffu, idx, k);
        float2 v = *(const float2*)&d_h[(size_t)nb * 64 + lane * 2];
        m.x = fmaxf(m.x, v.x);
        m.y = fmaxf(m.y, v.y);
    }
    *(float2*)&d_hc[(size_t)warp * 192 + lane * 2] = m;
}

// ---------------- mlp3 + mlp4 : h -> hc[:,64:192] ---------------------------
__global__ __launch_bounds__(256) void k_mlp34(const float* __restrict__ w3,
                                               const float* __restrict__ w4) {
    extern __shared__ float sm[];
    float* w3s = sm;           // 64*64
    float* w4s = sm + 4096;    // 128*64
    for (int i = threadIdx.x; i < 4096; i += 256) w3s[i] = w3[i];
    for (int i = threadIdx.x; i < 8192; i += 256) w4s[i] = w4[i];
    __syncthreads();

    int p = blockIdx.x * 256 + threadIdx.x;
    float h[64];
    const float* hin = d_h + (size_t)p * 64;
#pragma unroll
    for (int k = 0; k < 64; k += 4) {
        float4 v = *(const float4*)&hin[k];
        h[k] = v.x; h[k+1] = v.y; h[k+2] = v.z; h[k+3] = v.w;
    }

    float h3[64];
#pragma unroll
    for (int j = 0; j < 64; j += 4) {
        float a0 = 0.f, a1 = 0.f, a2 = 0.f, a3 = 0.f;
#pragma unroll
        for (int k = 0; k < 64; k += 4) {
            float4 b0 = *(const float4*)&w3s[(j + 0) * 64 + k];
            float4 b1 = *(const float4*)&w3s[(j + 1) * 64 + k];
            float4 b2 = *(const float4*)&w3s[(j + 2) * 64 + k];
            float4 b3 = *(const float4*)&w3s[(j + 3) * 64 + k];
            a0 += b0.x*h[k] + b0.y*h[k+1] + b0.z*h[k+2] + b0.w*h[k+3];
            a1 += b1.x*h[k] + b1.y*h[k+1] + b1.z*h[k+2] + b1.w*h[k+3];
            a2 += b2.x*h[k] + b2.y*h[k+1] + b2.z*h[k+2] + b2.w*h[k+3];
            a3 += b3.x*h[k] + b3.y*h[k+1] + b3.z*h[k+2] + b3.w*h[k+3];
        }
        h3[j]   = fmaxf(a0, 0.f);
        h3[j+1] = fmaxf(a1, 0.f);
        h3[j+2] = fmaxf(a2, 0.f);
        h3[j+3] = fmaxf(a3, 0.f);
    }

    float* out = d_hc + (size_t)p * 192 + 64;
#pragma unroll
    for (int j = 0; j < 128; j += 4) {
        float a0 = 0.f, a1 = 0.f, a2 = 0.f, a3 = 0.f;
#pragma unroll
        for (int k = 0; k < 64; k += 4) {
            float4 b0 = *(const float4*)&w4s[(j + 0) * 64 + k];
            float4 b1 = *(const float4*)&w4s[(j + 1) * 64 + k];
            float4 b2 = *(const float4*)&w4s[(j + 2) * 64 + k];
            float4 b3 = *(const float4*)&w4s[(j + 3) * 64 + k];
            a0 += b0.x*h3[k] + b0.y*h3[k+1] + b0.z*h3[k+2] + b0.w*h3[k+3];
            a1 += b1.x*h3[k] + b1.y*h3[k+1] + b1.z*h3[k+2] + b1.w*h3[k+3];
            a2 += b2.x*h3[k] + b2.y*h3[k+1] + b2.z*h3[k+2] + b2.w*h3[k+3];
            a3 += b3.x*h3[k] + b3.y*h3[k+1] + b3.z*h3[k+2] + b3.w*h3[k+3];
        }
        float4 r = make_float4(fmaxf(a0,0.f), fmaxf(a1,0.f), fmaxf(a2,0.f), fmaxf(a3,0.f));
        *(float4*)&out[j] = r;
    }
}

// ---------------- mlp5 GEMM fused with global max --------------------------
// C[m,n] = hc[m,:192] . w5[n,:192]; g[n] = max_m relu(C)  (relu via 0-init)
#define BM 128
#define BN 64
#define APAD 132         // BM + 4 (keeps float4 alignment, breaks bank stride)
#define BPAD 68          // BN + 4
#define G5_SMEM ((192 * APAD + 192 * BPAD) * 4)

__global__ __launch_bounds__(256) void k_gemm5max(const float* __restrict__ w5) {
    extern __shared__ float sm[];
    float* As = sm;                 // [192][APAD]
    float* Bs = sm + 192 * APAD;    // [192][BPAD]

    const int tid = threadIdx.x;
    const int m0 = blockIdx.y * BM;
    const int n0 = blockIdx.x * BN;

    // Stage A tile (hc rows) transposed: As[k][r]
    const float* Ablk = d_hc + (size_t)m0 * 192;
    for (int t = tid; t < BM * 48; t += 256) {
        int r = t / 48, kq = t % 48;
        float4 v = *(const float4*)&Ablk[(size_t)r * 192 + kq * 4];
        As[(kq * 4 + 0) * APAD + r] = v.x;
        As[(kq * 4 + 1) * APAD + r] = v.y;
        As[(kq * 4 + 2) * APAD + r] = v.z;
        As[(kq * 4 + 3) * APAD + r] = v.w;
    }
    // Stage B tile (w5 rows) transposed: Bs[k][c]
    for (int t = tid; t < BN * 48; t += 256) {
        int c = t / 48, kq = t % 48;
        float4 v = *(const float4*)&w5[(size_t)(n0 + c) * 192 + kq * 4];
        Bs[(kq * 4 + 0) * BPAD + c] = v.x;
        Bs[(kq * 4 + 1) * BPAD + c] = v.y;
        Bs[(kq * 4 + 2) * BPAD + c] = v.z;
        Bs[(kq * 4 + 3) * BPAD + c] = v.w;
    }
    __syncthreads();

    const int tx = tid & 15;   // 4 cols
    const int ty = tid >> 4;   // 8 rows

    float acc[8][4];
#pragma unroll
    for (int r = 0; r < 8; r++)
#pragma unroll
        for (int c = 0; c < 4; c++) acc[r][c] = 0.f;

#pragma unroll 8
    for (int k = 0; k < 192; k++) {
        float4 b  = *(const float4*)&Bs[k * BPAD + tx * 4];
        float4 a0 = *(const float4*)&As[k * APAD + ty * 8];
        float4 a1 = *(const float4*)&As[k * APAD + ty * 8 + 4];
        float a[8] = {a0.x, a0.y, a0.z, a0.w, a1.x, a1.y, a1.z, a1.w};
#pragma unroll
        for (int r = 0; r < 8; r++) {
            acc[r][0] += a[r] * b.x;
            acc[r][1] += a[r] * b.y;
            acc[r][2] += a[r] * b.z;
            acc[r][3] += a[r] * b.w;
        }
    }

    // per-thread max over its 8 rows
    float cm[4];
#pragma unroll
    for (int c = 0; c < 4; c++) {
        float m = acc[0][c];
#pragma unroll
        for (int r = 1; r < 8; r++) m = fmaxf(m, acc[r][c]);
        cm[c] = m;
    }

    __syncthreads();                 // reuse smem for column maxima
    int* smax = (int*)sm;
    if (tid < BN) smax[tid] = 0;     // 0 == 0.0f, also applies ReLU clamp
    __syncthreads();
#pragma unroll
    for (int c = 0; c < 4; c++)
        atomicMax(&smax[tx * 4 + c], __float_as_int(cm[c]));
    __syncthreads();
    if (tid < BN) atomicMax((int*)&d_g[n0 + tid], smax[tid]);
}

// ---------------- classifier head (warp per output) ------------------------
__global__ void k_head1(const float* __restrict__ wf1) {   // 1024 -> 512
    int out = blockIdx.x * 4 + (threadIdx.x >> 5);
    int lane = threadIdx.x & 31;
    const float* w = wf1 + (size_t)out * 1024;
    float s = 0.f;
    for (int k = lane; k < 1024; k += 32) s += d_g[k] * w[k];
#pragma unroll
    for (int o = 16; o; o >>= 1) s += __shfl_xor_sync(0xffffffffu, s, o);
    if (lane == 0) d_f1[out] = fmaxf(s, 0.f);
}
__global__ void k_head2(const float* __restrict__ wf2) {   // 512 -> 256
    int out = blockIdx.x * 4 + (threadIdx.x >> 5);
    int lane = threadIdx.x & 31;
    const float* w = wf2 + (size_t)out * 512;
    float s = 0.f;
    for (int k = lane; k < 512; k += 32) s += d_f1[k] * w[k];
#pragma unroll
    for (int o = 16; o; o >>= 1) s += __shfl_xor_sync(0xffffffffu, s, o);
    if (lane == 0) d_f2[out] = fmaxf(s, 0.f);
}
__global__ void k_head3(const float* __restrict__ wf3, float* __restrict__ out40) { // 256 -> 40
    int out = blockIdx.x * 4 + (threadIdx.x >> 5);
    int lane = threadIdx.x & 31;
    if (out >= 40) return;
    const float* w = wf3 + (size_t)out * 256;
    float s = 0.f;
    for (int k = lane; k < 256; k += 32) s += d_f2[k] * w[k];
#pragma unroll
    for (int o = 16; o; o >>= 1) s += __shfl_xor_sync(0xffffffffu, s, o);
    if (lane == 0) out40[out] = s;   // no relu on final layer
}

// ---------------- launcher --------------------------------------------------
extern "C" void kernel_launch(void* const* d_in, const int* in_sizes, int n_in,
                              void* d_out, int out_size) {
    const float* x       = (const float*)d_in[0];
    // d_in[1] = indptr (uniform degree K=16; unused)
    const int*   indices = (const int*)  d_in[2];
    const float* w1  = (const float*)d_in[3];
    const float* w2  = (const float*)d_in[4];
    const float* w3  = (const float*)d_in[5];
    const float* w4  = (const float*)d_in[6];
    const float* w5  = (const float*)d_in[7];
    const float* wf1 = (const float*)d_in[8];
    const float* wf2 = (const float*)d_in[9];
    const float* wf3 = (const float*)d_in[10];
    float* out = (float*)d_out;

    cudaFuncSetAttribute(k_mlp34,    cudaFuncAttributeMaxDynamicSharedMemorySize, 12288 * 4);
    cudaFuncSetAttribute(k_gemm5max, cudaFuncAttributeMaxDynamicSharedMemorySize, G5_SMEM);

    k_zero_g<<<1, 1024>>>();
    k_mlp12<<<NPTS / 256, 256>>>(x, w1, w2);
    k_pool <<<NPTS / 8, 256>>>(indices);
    k_mlp34<<<NPTS / 256, 256, 12288 * 4>>>(w3, w4);

    dim3 g5grid(1024 / BN, NPTS / BM);    // x = N-tile fastest -> L2 reuse of hc M-tile
    k_gemm5max<<<g5grid, 256, G5_SMEM>>>(w5);

    k_head1<<<512 / 4, 128>>>(wf1);
    k_head2<<<256 / 4, 128>>>(wf2);
    k_head3<<<10, 128>>>(wf3, out);
}

// round 7
// speedup vs baseline: 3.7976x; 3.7976x over previous
#include <cuda_runtime.h>
#include <cuda_bf16.h>
#include <math_constants.h>
#include <cstdint>

#define NPTS 262144
#define KNN  16

// ---------------- scratch globals ------------------------------------------
__device__ float d_h  [(size_t)NPTS * 64 ];
__device__ float d_h3 [(size_t)NPTS * 64 ];
__device__ float d_hc [(size_t)NPTS * 192];   // [x_gm | h4], tf32-rounded
__device__ float d_w5r[1024 * 192];           // w5 tf32-rounded
__device__ float d_g  [1024];
__device__ float d_f1 [512];
__device__ float d_f2 [256];

// ---------------- helpers ---------------------------------------------------
__device__ __forceinline__ float tf32r(float x) {
    float y;
    asm("cvt.rna.tf32.f32 %0, %1;" : "=f"(y) : "f"(x));
    return y;
}
__device__ __forceinline__ uint32_t smem_u32(const void* p) {
    uint32_t a;
    asm("{ .reg .u64 t; cvta.to.shared.u64 t, %1; cvt.u32.u64 %0, t; }" : "=r"(a) : "l"(p));
    return a;
}
__device__ __forceinline__ void cpasync16(uint32_t dst, const void* src) {
    asm volatile("cp.async.cg.shared.global [%0], [%1], 16;" :: "r"(dst), "l"(src));
}
__device__ __forceinline__ void cp_commit() { asm volatile("cp.async.commit_group;"); }
template<int N> __device__ __forceinline__ void cp_wait() {
    asm volatile("cp.async.wait_group %0;" :: "n"(N) : "memory");
}

// ---------------- init ------------------------------------------------------
__global__ void k_zero_g() {
    int t = blockIdx.x * blockDim.x + threadIdx.x;
    if (t < 1024) d_g[t] = 0.0f;
}
__global__ void k_round_w5(const float* __restrict__ w5) {
    int t = blockIdx.x * 256 + threadIdx.x;
    d_w5r[t] = tf32r(w5[t]);
}

// ---------------- mlp1 + mlp2 ----------------------------------------------
__global__ __launch_bounds__(256) void k_mlp12(const float* __restrict__ x,
                                               const float* __restrict__ w1,
                                               const float* __restrict__ w2) {
    __shared__ float w1s[64 * 3];
    __shared__ float w2s[64 * 64];
    for (int i = threadIdx.x; i < 192;  i += 256) w1s[i] = w1[i];
    for (int i = threadIdx.x; i < 4096; i += 256) w2s[i] = w2[i];
    __syncthreads();

    int p = blockIdx.x * 256 + threadIdx.x;
    float x0 = x[p * 3 + 0], x1 = x[p * 3 + 1], x2 = x[p * 3 + 2];

    float h1[64];
#pragma unroll
    for (int j = 0; j < 64; j++) {
        float a = x0 * w1s[j * 3] + x1 * w1s[j * 3 + 1] + x2 * w1s[j * 3 + 2];
        h1[j] = fmaxf(a, 0.0f);
    }
    float* out = d_h + (size_t)p * 64;
#pragma unroll
    for (int j = 0; j < 64; j += 4) {
        float a0 = 0.f, a1 = 0.f, a2 = 0.f, a3 = 0.f;
#pragma unroll
        for (int k = 0; k < 64; k += 4) {
            float4 b0 = *(const float4*)&w2s[(j + 0) * 64 + k];
            float4 b1 = *(const float4*)&w2s[(j + 1) * 64 + k];
            float4 b2 = *(const float4*)&w2s[(j + 2) * 64 + k];
            float4 b3 = *(const float4*)&w2s[(j + 3) * 64 + k];
            a0 += b0.x*h1[k] + b0.y*h1[k+1] + b0.z*h1[k+2] + b0.w*h1[k+3];
            a1 += b1.x*h1[k] + b1.y*h1[k+1] + b1.z*h1[k+2] + b1.w*h1[k+3];
            a2 += b2.x*h1[k] + b2.y*h1[k+1] + b2.z*h1[k+2] + b2.w*h1[k+3];
            a3 += b3.x*h1[k] + b3.y*h1[k+1] + b3.z*h1[k+2] + b3.w*h1[k+3];
        }
        *(float4*)&out[j] = make_float4(fmaxf(a0,0.f), fmaxf(a1,0.f),
                                        fmaxf(a2,0.f), fmaxf(a3,0.f));
    }
}

// ---------------- graph max-pool (writes hc[:,0:64], tf32-rounded) ----------
__global__ __launch_bounds__(256) void k_pool(const int* __restrict__ indices) {
    int warp = (blockIdx.x * blockDim.x + threadIdx.x) >> 5;
    int lane = threadIdx.x & 31;
    if (warp >= NPTS) return;
    int idx = indices[(size_t)warp * KNN + (lane & 15)];
    float2 m = make_float2(-CUDART_INF_F, -CUDART_INF_F);
#pragma unroll
    for (int k = 0; k < KNN; k++) {
        int nb = __shfl_sync(0xffffffffu, idx, k);
        float2 v = *(const float2*)&d_h[(size_t)nb * 64 + lane * 2];
        m.x = fmaxf(m.x, v.x);
        m.y = fmaxf(m.y, v.y);
    }
    m.x = tf32r(m.x); m.y = tf32r(m.y);
    *(float2*)&d_hc[(size_t)warp * 192 + lane * 2] = m;
}

// ---------------- mlp3 (h -> h3) --------------------------------------------
__global__ __launch_bounds__(256, 2) void k_mlp3(const float* __restrict__ w3) {
    __shared__ float w3s[4096];
    for (int i = threadIdx.x; i < 4096; i += 256) w3s[i] = w3[i];
    __syncthreads();
    int p = blockIdx.x * 256 + threadIdx.x;
    float h[64];
    const float* hin = d_h + (size_t)p * 64;
#pragma unroll
    for (int k = 0; k < 64; k += 4) {
        float4 v = *(const float4*)&hin[k];
        h[k] = v.x; h[k+1] = v.y; h[k+2] = v.z; h[k+3] = v.w;
    }
    float* out = d_h3 + (size_t)p * 64;
#pragma unroll
    for (int j = 0; j < 64; j += 4) {
        float a0 = 0.f, a1 = 0.f, a2 = 0.f, a3 = 0.f;
#pragma unroll
        for (int k = 0; k < 64; k += 4) {
            float4 b0 = *(const float4*)&w3s[(j + 0) * 64 + k];
            float4 b1 = *(const float4*)&w3s[(j + 1) * 64 + k];
            float4 b2 = *(const float4*)&w3s[(j + 2) * 64 + k];
            float4 b3 = *(const float4*)&w3s[(j + 3) * 64 + k];
            a0 += b0.x*h[k] + b0.y*h[k+1] + b0.z*h[k+2] + b0.w*h[k+3];
            a1 += b1.x*h[k] + b1.y*h[k+1] + b1.z*h[k+2] + b1.w*h[k+3];
            a2 += b2.x*h[k] + b2.y*h[k+1] + b2.z*h[k+2] + b2.w*h[k+3];
            a3 += b3.x*h[k] + b3.y*h[k+1] + b3.z*h[k+2] + b3.w*h[k+3];
        }
        *(float4*)&out[j] = make_float4(fmaxf(a0,0.f), fmaxf(a1,0.f),
                                        fmaxf(a2,0.f), fmaxf(a3,0.f));
    }
}

// ---------------- mlp4 (h3 -> hc[:,64:192], tf32-rounded) -------------------
__global__ __launch_bounds__(256, 2) void k_mlp4(const float* __restrict__ w4) {
    __shared__ float w4s[8192];
    for (int i = threadIdx.x; i < 8192; i += 256) w4s[i] = w4[i];
    __syncthreads();
    int p = blockIdx.x * 256 + threadIdx.x;
    float h[64];
    const float* hin = d_h3 + (size_t)p * 64;
#pragma unroll
    for (int k = 0; k < 64; k += 4) {
        float4 v = *(const float4*)&hin[k];
        h[k] = v.x; h[k+1] = v.y; h[k+2] = v.z; h[k+3] = v.w;
    }
    float* out = d_hc + (size_t)p * 192 + 64;
#pragma unroll
    for (int j = 0; j < 128; j += 4) {
        float a0 = 0.f, a1 = 0.f, a2 = 0.f, a3 = 0.f;
#pragma unroll
        for (int k = 0; k < 64; k += 4) {
            float4 b0 = *(const float4*)&w4s[(j + 0) * 64 + k];
            float4 b1 = *(const float4*)&w4s[(j + 1) * 64 + k];
            float4 b2 = *(const float4*)&w4s[(j + 2) * 64 + k];
            float4 b3 = *(const float4*)&w4s[(j + 3) * 64 + k];
            a0 += b0.x*h[k] + b0.y*h[k+1] + b0.z*h[k+2] + b0.w*h[k+3];
            a1 += b1.x*h[k] + b1.y*h[k+1] + b1.z*h[k+2] + b1.w*h[k+3];
            a2 += b2.x*h[k] + b2.y*h[k+1] + b2.z*h[k+2] + b2.w*h[k+3];
            a3 += b3.x*h[k] + b3.y*h[k+1] + b3.z*h[k+2] + b3.w*h[k+3];
        }
        *(float4*)&out[j] = make_float4(tf32r(fmaxf(a0,0.f)), tf32r(fmaxf(a1,0.f)),
                                        tf32r(fmaxf(a2,0.f)), tf32r(fmaxf(a3,0.f)));
    }
}

// ---------------- mlp5 via mma.sync tf32 + fused global max -----------------
// CTA 128(M) x 128(N) x 192(K); K chunks of 32, cp.async double-buffered.
// 8 warps = 4(m) x 2(n); warp tile 32x64 = 2x8 mma.m16n8k8 tiles.
// smem per buffer: A 128x(32+4pad) + B 128x36 floats = 36864 B; x2 = 73728 B.
#define G5_ROWPAD 36
#define G5_BUF_FLTS (128 * G5_ROWPAD)          // 4608 per matrix
#define G5_SMEM (2 * 2 * G5_BUF_FLTS * 4)      // 73728 bytes

__global__ __launch_bounds__(256) void k_gemm5max() {
    extern __shared__ __align__(16) float sm[];
    const uint32_t sbase = smem_u32(sm);
    const int tid  = threadIdx.x;
    const int wid  = tid >> 5;
    const int lane = tid & 31;
    const int g    = lane >> 2;        // group id (0..7)
    const int q    = lane & 3;         // thread in group (0..3)
    const int wm   = wid >> 1;         // warp m index 0..3
    const int wn   = wid & 1;          // warp n index 0..1
    const int m0 = blockIdx.y * 128;
    const int n0 = blockIdx.x * 128;

    const float* Ag = d_hc  + (size_t)m0 * 192;
    const float* Bg = d_w5r + (size_t)n0 * 192;

    auto stage = [&](int c, int b) {
        const int k0 = c * 32;
        uint32_t ab = sbase + b * (2 * G5_BUF_FLTS * 4);
        uint32_t bb = ab + G5_BUF_FLTS * 4;
#pragma unroll
        for (int i = 0; i < 4; i++) {
            int u = tid + i * 256;          // 0..1023
            int r = u >> 3, qq = u & 7;     // row 0..127, 16B quad 0..7
            cpasync16(ab + r * (G5_ROWPAD * 4) + qq * 16,
                      Ag + (size_t)r * 192 + k0 + qq * 4);
            cpasync16(bb + r * (G5_ROWPAD * 4) + qq * 16,
                      Bg + (size_t)r * 192 + k0 + qq * 4);
        }
        cp_commit();
    };

    float acc[2][8][4];
#pragma unroll
    for (int mt = 0; mt < 2; mt++)
#pragma unroll
        for (int nt = 0; nt < 8; nt++)
#pragma unroll
            for (int j = 0; j < 4; j++) acc[mt][nt][j] = 0.f;

    stage(0, 0);
    for (int ch = 0; ch < 6; ch++) {
        if (ch + 1 < 6) { stage(ch + 1, (ch + 1) & 1); cp_wait<1>(); }
        else            { cp_wait<0>(); }
        __syncthreads();

        const float* As = sm + (ch & 1) * (2 * G5_BUF_FLTS);
        const float* Bs = As + G5_BUF_FLTS;
        const float* Aw = As + (wm * 32 + g) * G5_ROWPAD;   // this thread's A rows
        const float* Bw = Bs + (wn * 64 + g) * G5_ROWPAD;   // this thread's B rows

#pragma unroll
        for (int ks = 0; ks < 4; ks++) {
            const int k0 = ks * 8 + q;
            float bf0[8], bf1[8];
#pragma unroll
            for (int nt = 0; nt < 8; nt++) {
                bf0[nt] = Bw[nt * 8 * G5_ROWPAD + k0];
                bf1[nt] = Bw[nt * 8 * G5_ROWPAD + k0 + 4];
            }
#pragma unroll
            for (int mt = 0; mt < 2; mt++) {
                float a0 = Aw[(mt * 16    ) * G5_ROWPAD + k0];
                float a1 = Aw[(mt * 16 + 8) * G5_ROWPAD + k0];
                float a2 = Aw[(mt * 16    ) * G5_ROWPAD + k0 + 4];
                float a3 = Aw[(mt * 16 + 8) * G5_ROWPAD + k0 + 4];
#pragma unroll
                for (int nt = 0; nt < 8; nt++) {
                    asm volatile(
                        "mma.sync.aligned.m16n8k8.row.col.f32.tf32.tf32.f32 "
                        "{%0,%1,%2,%3}, {%4,%5,%6,%7}, {%8,%9}, {%0,%1,%2,%3};"
                        : "+f"(acc[mt][nt][0]), "+f"(acc[mt][nt][1]),
                          "+f"(acc[mt][nt][2]), "+f"(acc[mt][nt][3])
                        : "r"(__float_as_uint(a0)), "r"(__float_as_uint(a1)),
                          "r"(__float_as_uint(a2)), "r"(__float_as_uint(a3)),
                          "r"(__float_as_uint(bf0[nt])), "r"(__float_as_uint(bf1[nt])));
                }
            }
        }
        __syncthreads();
    }

    // fused column-max epilogue (0-init == ReLU clamp); C cols: wn*64+nt*8+2q(+1)
    int* smax = (int*)sm;
    if (tid < 128) smax[tid] = 0;
    __syncthreads();
#pragma unroll
    for (int nt = 0; nt < 8; nt++) {
        float ve = fmaxf(fmaxf(acc[0][nt][0], acc[0][nt][2]),
                         fmaxf(acc[1][nt][0], acc[1][nt][2]));
        float vo = fmaxf(fmaxf(acc[0][nt][1], acc[0][nt][3]),
                         fmaxf(acc[1][nt][1], acc[1][nt][3]));
        int col = wn * 64 + nt * 8 + q * 2;
        atomicMax(&smax[col],     __float_as_int(ve));
        atomicMax(&smax[col + 1], __float_as_int(vo));
    }
    __syncthreads();
    if (tid < 128) atomicMax((int*)&d_g[n0 + tid], smax[tid]);
}

// ---------------- classifier head -------------------------------------------
__global__ void k_head1(const float* __restrict__ wf1) {
    int out = blockIdx.x * 4 + (threadIdx.x >> 5);
    int lane = threadIdx.x & 31;
    const float* w = wf1 + (size_t)out * 1024;
    float s = 0.f;
    for (int k = lane; k < 1024; k += 32) s += d_g[k] * w[k];
#pragma unroll
    for (int o = 16; o; o >>= 1) s += __shfl_xor_sync(0xffffffffu, s, o);
    if (lane == 0) d_f1[out] = fmaxf(s, 0.f);
}
__global__ void k_head2(const float* __restrict__ wf2) {
    int out = blockIdx.x * 4 + (threadIdx.x >> 5);
    int lane = threadIdx.x & 31;
    const float* w = wf2 + (size_t)out * 512;
    float s = 0.f;
    for (int k = lane; k < 512; k += 32) s += d_f1[k] * w[k];
#pragma unroll
    for (int o = 16; o; o >>= 1) s += __shfl_xor_sync(0xffffffffu, s, o);
    if (lane == 0) d_f2[out] = fmaxf(s, 0.f);
}
__global__ void k_head3(const float* __restrict__ wf3, float* __restrict__ out40) {
    int out = blockIdx.x * 4 + (threadIdx.x >> 5);
    int lane = threadIdx.x & 31;
    if (out >= 40) return;
    const float* w = wf3 + (size_t)out * 256;
    float s = 0.f;
    for (int k = lane; k < 256; k += 32) s += d_f2[k] * w[k];
#pragma unroll
    for (int o = 16; o; o >>= 1) s += __shfl_xor_sync(0xffffffffu, s, o);
    if (lane == 0) out40[out] = s;
}

// ---------------- launcher --------------------------------------------------
extern "C" void kernel_launch(void* const* d_in, const int* in_sizes, int n_in,
                              void* d_out, int out_size) {
    const float* x       = (const float*)d_in[0];
    const int*   indices = (const int*)  d_in[2];
    const float* w1  = (const float*)d_in[3];
    const float* w2  = (const float*)d_in[4];
    const float* w3  = (const float*)d_in[5];
    const float* w4  = (const float*)d_in[6];
    const float* w5  = (const float*)d_in[7];
    const float* wf1 = (const float*)d_in[8];
    const float* wf2 = (const float*)d_in[9];
    const float* wf3 = (const float*)d_in[10];
    float* out = (float*)d_out;

    cudaFuncSetAttribute(k_gemm5max, cudaFuncAttributeMaxDynamicSharedMemorySize, G5_SMEM);

    k_zero_g<<<1, 1024>>>();
    k_round_w5<<<1024 * 192 / 256, 256>>>(w5);
    k_mlp12<<<NPTS / 256, 256>>>(x, w1, w2);
    k_pool <<<NPTS / 8, 256>>>(indices);
    k_mlp3 <<<NPTS / 256, 256>>>(w3);
    k_mlp4 <<<NPTS / 256, 256>>>(w4);

    dim3 g5(1024 / 128, NPTS / 128);      // x = 8 N-tiles fastest (L2 reuse of A)
    k_gemm5max<<<g5, 256, G5_SMEM>>>();

    k_head1<<<512 / 4, 128>>>(wf1);
    k_head2<<<256 / 4, 128>>>(wf2);
    k_head3<<<10, 128>>>(wf3, out);
}